// round 1
// baseline (speedup 1.0000x reference)
#include <cuda_runtime.h>

#define Hc 128
#define Wc 128
#define Cc 64
#define COUTc 64
#define Bc 4
#define KKc 9

// Scratch (allocation-free: __device__ globals)
__device__ float g_xT[Bc*Hc*Wc*Cc];        // NHWC transposed input (16.8 MB)
__device__ float g_offs[Bc*Hc*Wc*18];      // offsets per pixel [pix][18]
__device__ float g_wK[KKc*Cc*COUTc];       // main weight rearranged [k][c][co]

// ---------------------------------------------------------------------------
// Kernel 1: NCHW -> NHWC transpose of x. One block per (b, y) row.
// ---------------------------------------------------------------------------
__global__ void __launch_bounds__(256) transpose_kernel(const float* __restrict__ x)
{
    __shared__ float sm[64 * 129];
    int by  = blockIdx.x;          // b*H + y
    int b   = by >> 7;
    int y   = by & 127;
    int tid = threadIdx.x;

    #pragma unroll
    for (int i = 0; i < 32; ++i) {
        int idx = tid + 256 * i;            // 8192 elements
        int c  = idx >> 7;
        int xx = idx & 127;
        sm[c * 129 + xx] = x[((size_t)(b * Cc + c) * Hc + y) * Wc + xx];
    }
    __syncthreads();
    float* op = g_xT + (size_t)(b * Hc + y) * Wc * Cc;
    #pragma unroll
    for (int i = 0; i < 32; ++i) {
        int idx = tid + 256 * i;
        int c  = idx & 63;
        int xx = idx >> 6;
        op[idx] = sm[c * 129 + xx];
    }
}

// ---------------------------------------------------------------------------
// Kernel 2: rearrange main conv weight [co][c][k] -> [k][c][co]
// ---------------------------------------------------------------------------
__global__ void rearrange_w_kernel(const float* __restrict__ w)
{
    int idx = blockIdx.x * 256 + threadIdx.x;
    if (idx < KKc * Cc * COUTc) {
        int k  = idx / (Cc * COUTc);
        int r  = idx - k * (Cc * COUTc);
        int c  = r >> 6;
        int co = r & 63;
        g_wK[idx] = w[(co * Cc + c) * KKc + k];
    }
}

// ---------------------------------------------------------------------------
// Kernel 3: offset conv 3x3 (C=64 -> 18 channels), zero padding.
// One pixel per thread, 18(+2 pad) register accumulators.
// ---------------------------------------------------------------------------
__global__ void __launch_bounds__(256) offset_conv_kernel(
    const float* __restrict__ ow, const float* __restrict__ ob)
{
    __shared__ float wsm[9 * 64 * 20];   // [tap][c][o padded to 20]
    int tid = threadIdx.x;

    for (int idx = tid; idx < 9 * 64 * 20; idx += 256) {
        int tap = idx / 1280;
        int r   = idx - tap * 1280;
        int c   = r / 20;
        int o   = r - c * 20;
        wsm[idx] = (o < 18) ? ow[(o * Cc + c) * 9 + tap] : 0.f;
    }
    __syncthreads();

    int pix = blockIdx.x * 256 + tid;
    int b = pix >> 14;
    int y = (pix >> 7) & 127;
    int x = pix & 127;

    float acc[20];
    #pragma unroll
    for (int o = 0; o < 20; ++o) acc[o] = (o < 18) ? ob[o] : 0.f;

    #pragma unroll
    for (int tap = 0; tap < 9; ++tap) {
        int yy = y + tap / 3 - 1;
        int xx = x + tap % 3 - 1;
        if (yy < 0 || yy >= Hc || xx < 0 || xx >= Wc) continue;
        const float4* xp = (const float4*)(g_xT + (size_t)((b * Hc + yy) * Wc + xx) * Cc);
        const float* wt = &wsm[tap * 1280];
        #pragma unroll 4
        for (int c4 = 0; c4 < 16; ++c4) {
            float4 xv = xp[c4];
            float xs[4] = {xv.x, xv.y, xv.z, xv.w};
            #pragma unroll
            for (int j = 0; j < 4; ++j) {
                const float4* wr = (const float4*)&wt[(c4 * 4 + j) * 20];
                #pragma unroll
                for (int o4 = 0; o4 < 5; ++o4) {
                    float4 wv = wr[o4];
                    acc[o4 * 4 + 0] += xs[j] * wv.x;
                    acc[o4 * 4 + 1] += xs[j] * wv.y;
                    acc[o4 * 4 + 2] += xs[j] * wv.z;
                    acc[o4 * 4 + 3] += xs[j] * wv.w;
                }
            }
        }
    }
    float* op = g_offs + (size_t)pix * 18;
    #pragma unroll
    for (int o = 0; o < 18; ++o) op[o] = acc[o];
}

// ---------------------------------------------------------------------------
// Kernel 4: fused deformable sampling + implicit GEMM.
// Block: 64 consecutive pixels (same b,y) x 64 output channels, 256 threads.
// Per k: stage W-chunk [64c x 64co] + per-pixel bilinear coords in SMEM,
// cooperatively sample into patch[p][c] (conflict-free STS.128), then
// 4co x 4px register-blocked outer-product GEMM.
// ---------------------------------------------------------------------------
__global__ void __launch_bounds__(256) dcn_main_kernel(
    const float* __restrict__ bias, float* __restrict__ out)
{
    __shared__ float patch[64 * 64];   // [p][c]
    __shared__ float wsm[64 * 64];     // [c][co]
    __shared__ float cw[4][64];        // bilinear corner weights per pixel
    __shared__ int   cidx[4][64];      // corner base index in float4 units

    int tid = threadIdx.x;
    int px0 = blockIdx.x * 64;
    int b   = px0 >> 14;
    int y   = (px0 >> 7) & 127;
    int x0  = px0 & 127;

    int co4     = (tid & 15) * 4;   // GEMM: output-channel group
    int pb      = (tid >> 4) * 4;   // GEMM: pixel group
    int s_cg    = tid & 15;         // sampling: channel group (float4)
    int s_pbase = tid >> 4;         // sampling: pixel base

    float acc[4][4];
    #pragma unroll
    for (int i = 0; i < 4; ++i)
        #pragma unroll
        for (int j = 0; j < 4; ++j) acc[i][j] = 0.f;

    const float4* xT4 = (const float4*)g_xT;

    for (int k = 0; k < 9; ++k) {
        // -- phase 1: stage weight chunk + bilinear coords --
        const float4* wg  = (const float4*)(g_wK + k * 4096);
        float4*       ws4 = (float4*)wsm;
        #pragma unroll
        for (int i = 0; i < 4; ++i) ws4[tid + 256 * i] = wg[tid + 256 * i];

        if (tid < 64) {
            int p = tid;
            const float* of = g_offs + (size_t)(px0 + p) * 18;
            float dy = of[2 * k];
            float dx = of[2 * k + 1];
            int   ky = k / 3;
            int   kx = k - ky * 3;
            float py  = (float)(y - 1 + ky) + dy;
            float pxx = (float)(x0 + p - 1 + kx) + dx;
            float fy = floorf(py), fx = floorf(pxx);
            float ly = py - fy,    lx = pxx - fx;
            int y0 = (int)fy, xq = (int)fx;
            bool vy0 = (y0 >= 0)     & (y0 < Hc);
            bool vy1 = (y0 + 1 >= 0) & (y0 + 1 < Hc);
            bool vx0 = (xq >= 0)     & (xq < Wc);
            bool vx1 = (xq + 1 >= 0) & (xq + 1 < Wc);
            float w00 = (1.f - ly) * (1.f - lx) * (float)(vy0 && vx0);
            float w01 = (1.f - ly) * lx         * (float)(vy0 && vx1);
            float w10 = ly * (1.f - lx)         * (float)(vy1 && vx0);
            float w11 = ly * lx                 * (float)(vy1 && vx1);
            int yc0 = min(max(y0, 0), Hc - 1);
            int yc1 = min(max(y0 + 1, 0), Hc - 1);
            int xc0 = min(max(xq, 0), Wc - 1);
            int xc1 = min(max(xq + 1, 0), Wc - 1);
            int rowb0 = (b * Hc + yc0) * Wc;
            int rowb1 = (b * Hc + yc1) * Wc;
            cidx[0][p] = (rowb0 + xc0) * 16;  cw[0][p] = w00;
            cidx[1][p] = (rowb0 + xc1) * 16;  cw[1][p] = w01;
            cidx[2][p] = (rowb1 + xc0) * 16;  cw[2][p] = w10;
            cidx[3][p] = (rowb1 + xc1) * 16;  cw[3][p] = w11;
        }
        __syncthreads();

        // -- phase 2: bilinear sampling into patch[p][c] --
        #pragma unroll
        for (int i = 0; i < 4; ++i) {
            int p = s_pbase + 16 * i;
            float4 v00 = xT4[cidx[0][p] + s_cg];
            float4 v01 = xT4[cidx[1][p] + s_cg];
            float4 v10 = xT4[cidx[2][p] + s_cg];
            float4 v11 = xT4[cidx[3][p] + s_cg];
            float w00 = cw[0][p], w01 = cw[1][p], w10 = cw[2][p], w11 = cw[3][p];
            float4 r;
            r.x = w00 * v00.x + w01 * v01.x + w10 * v10.x + w11 * v11.x;
            r.y = w00 * v00.y + w01 * v01.y + w10 * v10.y + w11 * v11.y;
            r.z = w00 * v00.z + w01 * v01.z + w10 * v10.z + w11 * v11.z;
            r.w = w00 * v00.w + w01 * v01.w + w10 * v10.w + w11 * v11.w;
            *(float4*)&patch[p * 64 + s_cg * 4] = r;
        }
        __syncthreads();

        // -- phase 3: register-blocked GEMM: acc[4px][4co] += patch @ W --
        #pragma unroll 4
        for (int c4 = 0; c4 < 16; ++c4) {
            float pm[4][4], wm[4][4];
            #pragma unroll
            for (int i = 0; i < 4; ++i) {
                float4 pv = *(const float4*)&patch[(pb + i) * 64 + c4 * 4];
                pm[i][0] = pv.x; pm[i][1] = pv.y; pm[i][2] = pv.z; pm[i][3] = pv.w;
            }
            #pragma unroll
            for (int j = 0; j < 4; ++j) {
                float4 wv = *(const float4*)&wsm[(c4 * 4 + j) * 64 + co4];
                wm[j][0] = wv.x; wm[j][1] = wv.y; wm[j][2] = wv.z; wm[j][3] = wv.w;
            }
            #pragma unroll
            for (int i = 0; i < 4; ++i)
                #pragma unroll
                for (int j = 0; j < 4; ++j)
                    #pragma unroll
                    for (int m = 0; m < 4; ++m)
                        acc[i][m] += pm[i][j] * wm[j][m];
        }
        __syncthreads();
    }

    // -- epilogue: add bias, store NCHW --
    #pragma unroll
    for (int m = 0; m < 4; ++m) {
        float bm = bias[co4 + m];
        float4 o;
        o.x = acc[0][m] + bm;
        o.y = acc[1][m] + bm;
        o.z = acc[2][m] + bm;
        o.w = acc[3][m] + bm;
        *(float4*)&out[((size_t)(b * COUTc + co4 + m) * Hc + y) * Wc + x0 + pb] = o;
    }
}

// ---------------------------------------------------------------------------
extern "C" void kernel_launch(void* const* d_in, const int* in_sizes, int n_in,
                              void* d_out, int out_size)
{
    const float* x      = (const float*)d_in[0];  // [4,64,128,128]
    const float* weight = (const float*)d_in[1];  // [64,64,3,3]
    const float* bias   = (const float*)d_in[2];  // [64]
    const float* ow     = (const float*)d_in[3];  // [18,64,3,3]
    const float* ob     = (const float*)d_in[4];  // [18]
    float* out = (float*)d_out;                   // [4,64,128,128]

    transpose_kernel<<<Bc * Hc, 256>>>(x);
    rearrange_w_kernel<<<(KKc * Cc * COUTc + 255) / 256, 256>>>(weight);
    offset_conv_kernel<<<(Bc * Hc * Wc) / 256, 256>>>(ow, ob);
    dcn_main_kernel<<<(Bc * Hc * Wc) / 64, 256>>>(bias, out);
}

// round 3
// speedup vs baseline: 1.1965x; 1.1965x over previous
#include <cuda_runtime.h>
#include <cstdint>

#define Hc 128
#define Wc 128
#define Cc 64
#define COUTc 64
#define Bc 4

// ------------------------------ scratch ------------------------------------
__device__ float4 g_xT4[Bc*Hc*Wc*(Cc/4)];   // NHWC input, float4 over C
__device__ float  g_offs[Bc*Hc*Wc*18];      // per-pixel offsets [pix][18]
__device__ float  g_wK[9*Cc*COUTc];         // weights [tap][c][co], tf32-rounded

// ------------------------------ helpers ------------------------------------
__device__ __forceinline__ uint32_t f2tf32(float x) {
    uint32_t r; asm("cvt.rna.tf32.f32 %0, %1;" : "=r"(r) : "f"(x)); return r;
}
__device__ __forceinline__ float f2tf32f(float x) {
    return __uint_as_float(f2tf32(x));
}
__device__ __forceinline__ void mma8(float* d, const uint32_t* a,
                                     uint32_t b0, uint32_t b1) {
    asm volatile(
        "mma.sync.aligned.m16n8k8.row.col.f32.tf32.tf32.f32 "
        "{%0,%1,%2,%3}, {%4,%5,%6,%7}, {%8,%9}, {%0,%1,%2,%3};"
        : "+f"(d[0]), "+f"(d[1]), "+f"(d[2]), "+f"(d[3])
        : "r"(a[0]), "r"(a[1]), "r"(a[2]), "r"(a[3]), "r"(b0), "r"(b1));
}

// ---------------------------------------------------------------------------
// Kernel 1: NCHW -> NHWC transpose of x.
// ---------------------------------------------------------------------------
__global__ void __launch_bounds__(256) transpose_kernel(const float* __restrict__ x)
{
    __shared__ float sm[64 * 129];
    int by = blockIdx.x, b = by >> 7, y = by & 127, tid = threadIdx.x;
    #pragma unroll
    for (int i = 0; i < 32; ++i) {
        int idx = tid + 256 * i;
        int c = idx >> 7, xx = idx & 127;
        sm[c * 129 + xx] = x[((size_t)(b * Cc + c) * Hc + y) * Wc + xx];
    }
    __syncthreads();
    float* op = (float*)g_xT4 + (size_t)(b * Hc + y) * Wc * Cc;
    #pragma unroll
    for (int i = 0; i < 32; ++i) {
        int idx = tid + 256 * i;
        int c = idx & 63, xx = idx >> 6;
        op[idx] = sm[c * 129 + xx];
    }
}

// ---------------------------------------------------------------------------
// Kernel 2: weight [co][c][tap] -> [tap][c][co], rounded to tf32.
// ---------------------------------------------------------------------------
__global__ void rearrange_w_kernel(const float* __restrict__ w)
{
    int idx = blockIdx.x * 256 + threadIdx.x;
    if (idx < 9 * Cc * COUTc) {
        int tap = idx >> 12;
        int r   = idx & 4095;
        int c   = r >> 6;
        int co  = r & 63;
        g_wK[idx] = f2tf32f(w[(co * Cc + c) * 9 + tap]);
    }
}

// ---------------------------------------------------------------------------
// Kernel 3: offset conv as implicit GEMM with tf32 mma.
// Block = 1 image row (128 px), 128 threads (4 warps).
// Warp tile: 32 px (2 m16 tiles) x 24 out-ch (3 n8 tiles). K = 9 taps x 64c.
// smem: xrow[130][64] (stride 68) + owsm[9][64][24] (stride 24, bank-exact).
// ---------------------------------------------------------------------------
#define XR_STR 68
__global__ void __launch_bounds__(128) offset_conv_kernel(
    const float* __restrict__ ow, const float* __restrict__ ob)
{
    extern __shared__ float sm[];
    float* xrow = sm;                  // 130*68 = 8840 floats
    float* owsm = sm + 8840;           // 13824 floats

    int tid = threadIdx.x, warp = tid >> 5, lane = tid & 31;
    int g = lane >> 2, tg = lane & 3;
    int blk = blockIdx.x, b = blk >> 7, y = blk & 127;

    // stage offset weights [tap][c][o<24], tf32-rounded, zero-padded o>=18
    for (int idx = tid; idx < 13824; idx += 128) {
        int tap = idx / 1536;
        int r = idx - tap * 1536;
        int c = r / 24, o = r - c * 24;
        float v = (o < 18) ? ow[(o * Cc + c) * 9 + tap] : 0.f;
        owsm[idx] = f2tf32f(v);
    }

    float acc[2][3][4];
    #pragma unroll
    for (int mt = 0; mt < 2; ++mt)
        #pragma unroll
        for (int nt = 0; nt < 3; ++nt) {
            int col = 8 * nt + 2 * tg;
            float b0 = (col < 18) ? ob[col] : 0.f;
            float b1 = (col + 1 < 18) ? ob[col + 1] : 0.f;
            acc[mt][nt][0] = b0; acc[mt][nt][1] = b1;
            acc[mt][nt][2] = b0; acc[mt][nt][3] = b1;
        }

    for (int ky = 0; ky < 3; ++ky) {
        int yy = y + ky - 1;
        bool rok = (yy >= 0) && (yy < Hc);
        __syncthreads();
        // stage padded input row xrow[xi = x+1][c], zeros at borders
        for (int i = 0; i < 17; ++i) {
            int j4 = tid + 128 * i;
            if (j4 < 2080) {
                int xi = j4 >> 4, cg = j4 & 15, x = xi - 1;
                float4 v = make_float4(0.f, 0.f, 0.f, 0.f);
                if (rok && x >= 0 && x < Wc)
                    v = g_xT4[((size_t)(b * Hc + yy) * Wc + x) * 16 + cg];
                v.x = f2tf32f(v.x); v.y = f2tf32f(v.y);
                v.z = f2tf32f(v.z); v.w = f2tf32f(v.w);
                *(float4*)&xrow[xi * XR_STR + cg * 4] = v;
            }
        }
        __syncthreads();
        if (rok) {
            for (int kx = 0; kx < 3; ++kx) {
                const float* wt = owsm + (ky * 3 + kx) * 1536;
                int xbase = warp * 32 + g + kx;
                #pragma unroll
                for (int s = 0; s < 8; ++s) {
                    int k0 = 8 * s;
                    uint32_t a[2][4];
                    #pragma unroll
                    for (int mt = 0; mt < 2; ++mt) {
                        int xi = xbase + 16 * mt;
                        a[mt][0] = __float_as_uint(xrow[xi * XR_STR + k0 + tg]);
                        a[mt][1] = __float_as_uint(xrow[(xi + 8) * XR_STR + k0 + tg]);
                        a[mt][2] = __float_as_uint(xrow[xi * XR_STR + k0 + tg + 4]);
                        a[mt][3] = __float_as_uint(xrow[(xi + 8) * XR_STR + k0 + tg + 4]);
                    }
                    #pragma unroll
                    for (int nt = 0; nt < 3; ++nt) {
                        uint32_t b0 = __float_as_uint(wt[(k0 + tg) * 24 + 8 * nt + g]);
                        uint32_t b1 = __float_as_uint(wt[(k0 + tg + 4) * 24 + 8 * nt + g]);
                        mma8(acc[0][nt], a[0], b0, b1);
                        mma8(acc[1][nt], a[1], b0, b1);
                    }
                }
            }
        }
    }

    // write offsets (cols >= 18 discarded; col even so pair fits when col<18)
    int pix0 = blk * 128;
    #pragma unroll
    for (int mt = 0; mt < 2; ++mt)
        #pragma unroll
        for (int nt = 0; nt < 3; ++nt) {
            int col = 8 * nt + 2 * tg;
            if (col < 18) {
                int p = warp * 32 + 16 * mt + g;
                *(float2*)&g_offs[(size_t)(pix0 + p) * 18 + col] =
                    make_float2(acc[mt][nt][0], acc[mt][nt][1]);
                *(float2*)&g_offs[(size_t)(pix0 + p + 8) * 18 + col] =
                    make_float2(acc[mt][nt][2], acc[mt][nt][3]);
            }
        }
}

// ---------------------------------------------------------------------------
// Kernel 4: fused deformable sampling + tf32 mma GEMM.
// Block = 1 image row (128 px) x 64 co, 128 threads (4 warps).
// Warp tile: 32 px (2 m16) x 64 co (8 n8). 64 accum regs/thread.
// smem floats: patch[128][68] @0 (8704) | wsm[64][72] @8704 (4608)
//              cw4 @13312 (512) | cidx4 @13824 (512) | bias @14336 (64)
// ---------------------------------------------------------------------------
#define P_STR 68
#define W_STR 72
#define SM_MAIN_FLOATS 14400
__global__ void __launch_bounds__(128) dcn_main_kernel(
    const float* __restrict__ bias, float* __restrict__ out)
{
    extern __shared__ float sm[];
    float*  patch = sm;
    float*  wsm   = sm + 8704;
    float4* cw4   = (float4*)(sm + 13312);
    int4*   cidx4 = (int4*)(sm + 13824);
    float*  bsm   = sm + 14336;

    int tid = threadIdx.x, warp = tid >> 5, lane = tid & 31;
    int g = lane >> 2, tg = lane & 3;
    int blk = blockIdx.x, b = blk >> 7, y = blk & 127;

    if (tid < 64) bsm[tid] = bias[tid];

    float acc[2][8][4];
    #pragma unroll
    for (int mt = 0; mt < 2; ++mt)
        #pragma unroll
        for (int nt = 0; nt < 8; ++nt)
            #pragma unroll
            for (int j = 0; j < 4; ++j) acc[mt][nt][j] = 0.f;

    int s_cg = tid & 15, s_p0 = tid >> 4;

    for (int k = 0; k < 9; ++k) {
        __syncthreads();
        // stage weight tile [c][co] -> wsm stride 72
        {
            const float4* src = (const float4*)(g_wK + k * 4096);
            #pragma unroll
            for (int i = 0; i < 8; ++i) {
                int j4 = tid + 128 * i;
                int kr = j4 >> 4, n4 = j4 & 15;
                *(float4*)&wsm[kr * W_STR + n4 * 4] = src[j4];
            }
        }
        // per-pixel bilinear coords (tid == pixel)
        {
            int p = tid;
            const float* of = g_offs + (size_t)(blk * 128 + p) * 18;
            float dy = of[2 * k], dx = of[2 * k + 1];
            int ky = k / 3, kx = k - ky * 3;
            float py  = (float)(y - 1 + ky) + dy;
            float pxx = (float)(p - 1 + kx) + dx;
            float fy = floorf(py), fx = floorf(pxx);
            float ly = py - fy, lx = pxx - fx;
            int y0 = (int)fy, xq = (int)fx;
            bool vy0 = (y0 >= 0) & (y0 < Hc);
            bool vy1 = (y0 + 1 >= 0) & (y0 + 1 < Hc);
            bool vx0 = (xq >= 0) & (xq < Wc);
            bool vx1 = (xq + 1 >= 0) & (xq + 1 < Wc);
            float4 w4;
            w4.x = (1.f - ly) * (1.f - lx) * (float)(vy0 && vx0);
            w4.y = (1.f - ly) * lx         * (float)(vy0 && vx1);
            w4.z = ly * (1.f - lx)         * (float)(vy1 && vx0);
            w4.w = ly * lx                 * (float)(vy1 && vx1);
            int yc0 = min(max(y0, 0), Hc - 1);
            int yc1 = min(max(y0 + 1, 0), Hc - 1);
            int xc0 = min(max(xq, 0), Wc - 1);
            int xc1 = min(max(xq + 1, 0), Wc - 1);
            int r0 = (b * Hc + yc0) * Wc, r1 = (b * Hc + yc1) * Wc;
            cidx4[p] = make_int4((r0 + xc0) * 16, (r0 + xc1) * 16,
                                 (r1 + xc0) * 16, (r1 + xc1) * 16);
            cw4[p] = w4;
        }
        __syncthreads();
        // bilinear sampling into patch[p][c] (tf32-rounded)
        #pragma unroll
        for (int i = 0; i < 16; ++i) {
            int p = s_p0 + 8 * i;
            int4  ci = cidx4[p];
            float4 w4 = cw4[p];
            float4 v00 = g_xT4[ci.x + s_cg];
            float4 v01 = g_xT4[ci.y + s_cg];
            float4 v10 = g_xT4[ci.z + s_cg];
            float4 v11 = g_xT4[ci.w + s_cg];
            float4 r;
            r.x = w4.x*v00.x + w4.y*v01.x + w4.z*v10.x + w4.w*v11.x;
            r.y = w4.x*v00.y + w4.y*v01.y + w4.z*v10.y + w4.w*v11.y;
            r.z = w4.x*v00.z + w4.y*v01.z + w4.z*v10.z + w4.w*v11.z;
            r.w = w4.x*v00.w + w4.y*v01.w + w4.z*v10.w + w4.w*v11.w;
            r.x = f2tf32f(r.x); r.y = f2tf32f(r.y);
            r.z = f2tf32f(r.z); r.w = f2tf32f(r.w);
            *(float4*)&patch[p * P_STR + s_cg * 4] = r;
        }
        __syncthreads();
        // warp-tile GEMM: 8 k-steps x (2 m-tiles x 8 n-tiles)
        #pragma unroll
        for (int s = 0; s < 8; ++s) {
            int k0 = 8 * s;
            uint32_t a[2][4];
            #pragma unroll
            for (int mt = 0; mt < 2; ++mt) {
                int r0 = warp * 32 + 16 * mt + g;
                a[mt][0] = __float_as_uint(patch[r0 * P_STR + k0 + tg]);
                a[mt][1] = __float_as_uint(patch[(r0 + 8) * P_STR + k0 + tg]);
                a[mt][2] = __float_as_uint(patch[r0 * P_STR + k0 + tg + 4]);
                a[mt][3] = __float_as_uint(patch[(r0 + 8) * P_STR + k0 + tg + 4]);
            }
            #pragma unroll
            for (int nt = 0; nt < 8; ++nt) {
                uint32_t b0 = __float_as_uint(wsm[(k0 + tg) * W_STR + 8 * nt + g]);
                uint32_t b1 = __float_as_uint(wsm[(k0 + tg + 4) * W_STR + 8 * nt + g]);
                mma8(acc[0][nt], a[0], b0, b1);
                mma8(acc[1][nt], a[1], b0, b1);
            }
        }
    }

    // epilogue: transpose through smem (stride 132 -> conflict-free), store NCHW
    __syncthreads();
    float* O = sm;   // reuse patch region: 64*132 = 8448 < 8704 floats
    #pragma unroll
    for (int mt = 0; mt < 2; ++mt)
        #pragma unroll
        for (int nt = 0; nt < 8; ++nt) {
            int row = warp * 32 + 16 * mt + g;
            int col = 8 * nt + 2 * tg;
            O[col * 132 + row]           = acc[mt][nt][0] + bsm[col];
            O[(col + 1) * 132 + row]     = acc[mt][nt][1] + bsm[col + 1];
            O[col * 132 + row + 8]       = acc[mt][nt][2] + bsm[col];
            O[(col + 1) * 132 + row + 8] = acc[mt][nt][3] + bsm[col + 1];
        }
    __syncthreads();
    #pragma unroll
    for (int i = 0; i < 16; ++i) {
        int j4 = tid + 128 * i;          // 2048 float4s
        int co = j4 >> 5, xq = j4 & 31;
        float4 v = *(float4*)&O[co * 132 + xq * 4];
        *(float4*)&out[(((size_t)b * COUTc + co) * Hc + y) * Wc + xq * 4] = v;
    }
}

// ---------------------------------------------------------------------------
extern "C" void kernel_launch(void* const* d_in, const int* in_sizes, int n_in,
                              void* d_out, int out_size)
{
    const float* x      = (const float*)d_in[0];
    const float* weight = (const float*)d_in[1];
    const float* bias   = (const float*)d_in[2];
    const float* ow     = (const float*)d_in[3];
    const float* ob     = (const float*)d_in[4];
    float* out = (float*)d_out;

    static int configured = 0;
    if (!configured) {
        cudaFuncSetAttribute(offset_conv_kernel,
            cudaFuncAttributeMaxDynamicSharedMemorySize, (8840 + 13824) * 4);
        cudaFuncSetAttribute(dcn_main_kernel,
            cudaFuncAttributeMaxDynamicSharedMemorySize, SM_MAIN_FLOATS * 4);
        configured = 1;
    }

    transpose_kernel<<<Bc * Hc, 256>>>(x);
    rearrange_w_kernel<<<(9 * Cc * COUTc + 255) / 256, 256>>>(weight);
    offset_conv_kernel<<<Bc * Hc, 128, (8840 + 13824) * 4>>>(ow, ob);
    dcn_main_kernel<<<Bc * Hc, 128, SM_MAIN_FLOATS * 4>>>(bias, out);
}

// round 4
// speedup vs baseline: 1.9167x; 1.6020x over previous
#include <cuda_runtime.h>
#include <cstdint>

#define Hc 128
#define Wc 128
#define Cc 64
#define COUTc 64
#define Bc 4

// ------------------------------ scratch ------------------------------------
__device__ float4 g_xT4[Bc*Hc*Wc*(Cc/4)];   // NHWC input, float4 over C
__device__ float2 g_offs2[9*Bc*Hc*Wc];      // offsets [tap][pix] (dy,dx)
__device__ float  g_wK[9*Cc*COUTc];         // main weights [tap][c][co] tf32
__device__ float  g_owR[9*Cc*24];           // offset weights [tap][c][24] tf32

// ------------------------------ helpers ------------------------------------
__device__ __forceinline__ uint32_t f2tf32(float x) {
    uint32_t r; asm("cvt.rna.tf32.f32 %0, %1;" : "=r"(r) : "f"(x)); return r;
}
__device__ __forceinline__ float f2tf32f(float x) {
    return __uint_as_float(f2tf32(x));
}
__device__ __forceinline__ void mma8(float* d, const uint32_t* a,
                                     uint32_t b0, uint32_t b1) {
    asm volatile(
        "mma.sync.aligned.m16n8k8.row.col.f32.tf32.tf32.f32 "
        "{%0,%1,%2,%3}, {%4,%5,%6,%7}, {%8,%9}, {%0,%1,%2,%3};"
        : "+f"(d[0]), "+f"(d[1]), "+f"(d[2]), "+f"(d[3])
        : "r"(a[0]), "r"(a[1]), "r"(a[2]), "r"(a[3]), "r"(b0), "r"(b1));
}

// ---------------------------------------------------------------------------
// Kernel 1: prep. blocks 0..511: NCHW->NHWC transpose; blocks 512+: weight
// rearrangement for both convs (tf32-rounded).
// ---------------------------------------------------------------------------
__global__ void __launch_bounds__(256) prep_kernel(
    const float* __restrict__ x, const float* __restrict__ w,
    const float* __restrict__ ow)
{
    int bid = blockIdx.x, tid = threadIdx.x;
    if (bid < 512) {
        __shared__ float sm[64 * 129];
        int b = bid >> 7, y = bid & 127;
        #pragma unroll
        for (int i = 0; i < 32; ++i) {
            int idx = tid + 256 * i;
            int c = idx >> 7, xx = idx & 127;
            sm[c * 129 + xx] = x[((size_t)(b * Cc + c) * Hc + y) * Wc + xx];
        }
        __syncthreads();
        float* op = (float*)g_xT4 + (size_t)(b * Hc + y) * Wc * Cc;
        #pragma unroll
        for (int i = 0; i < 32; ++i) {
            int idx = tid + 256 * i;
            int c = idx & 63, xx = idx >> 6;
            op[idx] = sm[c * 129 + xx];
        }
    } else {
        int t = (bid - 512) * 256 + tid;          // 0..9215
        for (int idx = t; idx < 9 * Cc * COUTc; idx += 36 * 256) {
            int tap = idx >> 12, r = idx & 4095;
            int c = r >> 6, co = r & 63;
            g_wK[idx] = f2tf32f(w[(co * Cc + c) * 9 + tap]);
        }
        for (int idx = t; idx < 9 * Cc * 24; idx += 36 * 256) {
            int tap = idx / 1536;
            int r = idx - tap * 1536;
            int c = r / 24, o = r - c * 24;
            g_owR[idx] = (o < 18) ? f2tf32f(ow[(o * Cc + c) * 9 + tap]) : 0.f;
        }
    }
}

// ---------------------------------------------------------------------------
// Kernel 2: offset conv as implicit GEMM (tf32 mma).
// Block = 1 image row (128 px), 256 threads (8 warps), warp tile 16px x 24ch.
// Weights staged per-ky (3 taps) to keep smem at 53.8KB -> 4 blocks/SM.
// smem: xrow[130][68] @0 (8840) | owsm3[3][64][24] @8840 (4608)
// ---------------------------------------------------------------------------
#define XR_STR 68
__global__ void __launch_bounds__(256) offset_conv_kernel(
    const float* __restrict__ ob)
{
    extern __shared__ float sm[];
    float* xrow  = sm;
    float* owsm3 = sm + 8840;

    int tid = threadIdx.x, warp = tid >> 5, lane = tid & 31;
    int g = lane >> 2, tg = lane & 3;
    int blk = blockIdx.x, b = blk >> 7, y = blk & 127;

    float acc[3][4];
    #pragma unroll
    for (int nt = 0; nt < 3; ++nt) {
        int col = 8 * nt + 2 * tg;
        float b0 = (col < 18) ? __ldg(&ob[col]) : 0.f;
        float b1 = (col + 1 < 18) ? __ldg(&ob[col + 1]) : 0.f;
        acc[nt][0] = b0; acc[nt][1] = b1; acc[nt][2] = b0; acc[nt][3] = b1;
    }

    for (int ky = 0; ky < 3; ++ky) {
        int yy = y + ky - 1;
        bool rok = (yy >= 0) && (yy < Hc);
        __syncthreads();
        // stage padded input row (tf32) + 3 taps of weights
        #pragma unroll
        for (int i = 0; i < 9; ++i) {
            int j4 = tid + 256 * i;
            if (j4 < 2080) {
                int xi = j4 >> 4, cg = j4 & 15, x = xi - 1;
                float4 v = make_float4(0.f, 0.f, 0.f, 0.f);
                if (rok && x >= 0 && x < Wc)
                    v = g_xT4[((size_t)(b * Hc + yy) * Wc + x) * 16 + cg];
                v.x = f2tf32f(v.x); v.y = f2tf32f(v.y);
                v.z = f2tf32f(v.z); v.w = f2tf32f(v.w);
                *(float4*)&xrow[xi * XR_STR + cg * 4] = v;
            }
        }
        {
            const float4* src = (const float4*)(g_owR + ky * 3 * 1536);
            float4* dst = (float4*)owsm3;
            #pragma unroll
            for (int i = 0; i < 5; ++i) {
                int j4 = tid + 256 * i;
                if (j4 < 1152) dst[j4] = src[j4];
            }
        }
        __syncthreads();
        if (rok) {
            #pragma unroll
            for (int kx = 0; kx < 3; ++kx) {
                const float* wt = owsm3 + kx * 1536;
                int xi = warp * 16 + g + kx;
                #pragma unroll
                for (int s = 0; s < 8; ++s) {
                    int k0 = 8 * s;
                    uint32_t a[4];
                    a[0] = __float_as_uint(xrow[xi * XR_STR + k0 + tg]);
                    a[1] = __float_as_uint(xrow[(xi + 8) * XR_STR + k0 + tg]);
                    a[2] = __float_as_uint(xrow[xi * XR_STR + k0 + tg + 4]);
                    a[3] = __float_as_uint(xrow[(xi + 8) * XR_STR + k0 + tg + 4]);
                    #pragma unroll
                    for (int nt = 0; nt < 3; ++nt) {
                        uint32_t b0 = __float_as_uint(wt[(k0 + tg) * 24 + 8 * nt + g]);
                        uint32_t b1 = __float_as_uint(wt[(k0 + tg + 4) * 24 + 8 * nt + g]);
                        mma8(acc[nt], a, b0, b1);
                    }
                }
            }
        }
    }

    // write offsets to [tap][pix] float2 layout
    int pix0 = blk * 128;
    #pragma unroll
    for (int nt = 0; nt < 3; ++nt) {
        int col = 8 * nt + 2 * tg;
        if (col < 18) {
            int tap = col >> 1;
            int p = warp * 16 + g;
            g_offs2[(size_t)tap * (Bc*Hc*Wc) + pix0 + p] =
                make_float2(acc[nt][0], acc[nt][1]);
            g_offs2[(size_t)tap * (Bc*Hc*Wc) + pix0 + p + 8] =
                make_float2(acc[nt][2], acc[nt][3]);
        }
    }
}

// ---------------------------------------------------------------------------
// Kernel 3: fused deformable sampling + tf32 mma GEMM.
// Block = 1 image row (128 px) x 64 co, 256 threads (8 warps).
// Warp tile: 32px (2 m16) x 32co (4 n8) -> 32 acc regs.
// smem floats: patch[128][68] @0 (8704) | wsm[64][72] @8704 (4608)
//              cw4 @13312 (512) | cidx4 @13824 (512)   total 57344B
// ---------------------------------------------------------------------------
#define P_STR 68
#define W_STR 72
#define SM_MAIN_FLOATS 14336
__global__ void __launch_bounds__(256) dcn_main_kernel(
    const float* __restrict__ bias, float* __restrict__ out)
{
    extern __shared__ float sm[];
    float*  patch = sm;
    float*  wsm   = sm + 8704;
    float4* cw4   = (float4*)(sm + 13312);
    int4*   cidx4 = (int4*)(sm + 13824);

    int tid = threadIdx.x, warp = tid >> 5, lane = tid & 31;
    int g = lane >> 2, tg = lane & 3;
    int mgrp = warp >> 1;             // 0..3: which 32-px group
    int ngrp = warp & 1;              // 0..1: which 32-co half
    int blk = blockIdx.x, b = blk >> 7, y = blk & 127;

    float acc[2][4][4];
    #pragma unroll
    for (int mt = 0; mt < 2; ++mt)
        #pragma unroll
        for (int nt = 0; nt < 4; ++nt)
            #pragma unroll
            for (int j = 0; j < 4; ++j) acc[mt][nt][j] = 0.f;

    int s_cg = tid & 15, s_p0 = tid >> 4;

    for (int k = 0; k < 9; ++k) {
        __syncthreads();
        // stage weight tile [c][co] -> wsm stride 72
        {
            const float4* src = (const float4*)(g_wK + k * 4096);
            #pragma unroll
            for (int i = 0; i < 4; ++i) {
                int j4 = tid + 256 * i;
                int kr = j4 >> 4, n4 = j4 & 15;
                *(float4*)&wsm[kr * W_STR + n4 * 4] = src[j4];
            }
        }
        // per-pixel bilinear coords
        if (tid < 128) {
            int p = tid;
            float2 d2 = g_offs2[(size_t)k * (Bc*Hc*Wc) + blk * 128 + p];
            int ky = k / 3, kx = k - ky * 3;
            float py  = (float)(y - 1 + ky) + d2.x;
            float pxx = (float)(p - 1 + kx) + d2.y;
            float fy = floorf(py), fx = floorf(pxx);
            float ly = py - fy, lx = pxx - fx;
            int y0 = (int)fy, xq = (int)fx;
            bool vy0 = (y0 >= 0) & (y0 < Hc);
            bool vy1 = (y0 + 1 >= 0) & (y0 + 1 < Hc);
            bool vx0 = (xq >= 0) & (xq < Wc);
            bool vx1 = (xq + 1 >= 0) & (xq + 1 < Wc);
            float4 w4;
            w4.x = (1.f - ly) * (1.f - lx) * (float)(vy0 && vx0);
            w4.y = (1.f - ly) * lx         * (float)(vy0 && vx1);
            w4.z = ly * (1.f - lx)         * (float)(vy1 && vx0);
            w4.w = ly * lx                 * (float)(vy1 && vx1);
            int yc0 = min(max(y0, 0), Hc - 1);
            int yc1 = min(max(y0 + 1, 0), Hc - 1);
            int xc0 = min(max(xq, 0), Wc - 1);
            int xc1 = min(max(xq + 1, 0), Wc - 1);
            int r0 = (b * Hc + yc0) * Wc, r1 = (b * Hc + yc1) * Wc;
            cidx4[p] = make_int4((r0 + xc0) * 16, (r0 + xc1) * 16,
                                 (r1 + xc0) * 16, (r1 + xc1) * 16);
            cw4[p] = w4;
        }
        __syncthreads();
        // bilinear sampling into patch[p][c]
        #pragma unroll
        for (int i = 0; i < 8; ++i) {
            int p = s_p0 + 16 * i;
            int4  ci = cidx4[p];
            float4 w4 = cw4[p];
            float4 v00 = g_xT4[ci.x + s_cg];
            float4 v01 = g_xT4[ci.y + s_cg];
            float4 v10 = g_xT4[ci.z + s_cg];
            float4 v11 = g_xT4[ci.w + s_cg];
            float4 r;
            r.x = w4.x*v00.x + w4.y*v01.x + w4.z*v10.x + w4.w*v11.x;
            r.y = w4.x*v00.y + w4.y*v01.y + w4.z*v10.y + w4.w*v11.y;
            r.z = w4.x*v00.z + w4.y*v01.z + w4.z*v10.z + w4.w*v11.z;
            r.w = w4.x*v00.w + w4.y*v01.w + w4.z*v10.w + w4.w*v11.w;
            r.x = f2tf32f(r.x); r.y = f2tf32f(r.y);
            r.z = f2tf32f(r.z); r.w = f2tf32f(r.w);
            *(float4*)&patch[p * P_STR + s_cg * 4] = r;
        }
        __syncthreads();
        // warp-tile GEMM: 8 k-steps x (2 m-tiles x 4 n-tiles)
        #pragma unroll
        for (int s = 0; s < 8; ++s) {
            int k0 = 8 * s;
            uint32_t a[2][4];
            #pragma unroll
            for (int mt = 0; mt < 2; ++mt) {
                int r0 = mgrp * 32 + 16 * mt + g;
                a[mt][0] = __float_as_uint(patch[r0 * P_STR + k0 + tg]);
                a[mt][1] = __float_as_uint(patch[(r0 + 8) * P_STR + k0 + tg]);
                a[mt][2] = __float_as_uint(patch[r0 * P_STR + k0 + tg + 4]);
                a[mt][3] = __float_as_uint(patch[(r0 + 8) * P_STR + k0 + tg + 4]);
            }
            #pragma unroll
            for (int nt = 0; nt < 4; ++nt) {
                int nc = ngrp * 32 + 8 * nt + g;
                uint32_t b0 = __float_as_uint(wsm[(k0 + tg) * W_STR + nc]);
                uint32_t b1 = __float_as_uint(wsm[(k0 + tg + 4) * W_STR + nc]);
                mma8(acc[0][nt], a[0], b0, b1);
                mma8(acc[1][nt], a[1], b0, b1);
            }
        }
    }

    // epilogue: transpose through smem (stride 132), add bias, store NCHW
    __syncthreads();
    float* O = sm;   // 64*132 = 8448 < 8704 floats
    #pragma unroll
    for (int mt = 0; mt < 2; ++mt)
        #pragma unroll
        for (int nt = 0; nt < 4; ++nt) {
            int row = mgrp * 32 + 16 * mt + g;
            int col = ngrp * 32 + 8 * nt + 2 * tg;
            float b0 = __ldg(&bias[col]), b1 = __ldg(&bias[col + 1]);
            O[col * 132 + row]           = acc[mt][nt][0] + b0;
            O[(col + 1) * 132 + row]     = acc[mt][nt][1] + b1;
            O[col * 132 + row + 8]       = acc[mt][nt][2] + b0;
            O[(col + 1) * 132 + row + 8] = acc[mt][nt][3] + b1;
        }
    __syncthreads();
    #pragma unroll
    for (int i = 0; i < 8; ++i) {
        int j4 = tid + 256 * i;          // 2048 float4s
        int co = j4 >> 5, xq = j4 & 31;
        float4 v = *(float4*)&O[co * 132 + xq * 4];
        *(float4*)&out[(((size_t)b * COUTc + co) * Hc + y) * Wc + xq * 4] = v;
    }
}

// ---------------------------------------------------------------------------
extern "C" void kernel_launch(void* const* d_in, const int* in_sizes, int n_in,
                              void* d_out, int out_size)
{
    const float* x      = (const float*)d_in[0];
    const float* weight = (const float*)d_in[1];
    const float* bias   = (const float*)d_in[2];
    const float* ow     = (const float*)d_in[3];
    const float* ob     = (const float*)d_in[4];
    float* out = (float*)d_out;

    static int configured = 0;
    if (!configured) {
        cudaFuncSetAttribute(offset_conv_kernel,
            cudaFuncAttributeMaxDynamicSharedMemorySize, (8840 + 4608) * 4);
        cudaFuncSetAttribute(dcn_main_kernel,
            cudaFuncAttributeMaxDynamicSharedMemorySize, SM_MAIN_FLOATS * 4);
        configured = 1;
    }

    prep_kernel<<<512 + 36, 256>>>(x, weight, ow);
    offset_conv_kernel<<<Bc * Hc, 256, (8840 + 4608) * 4>>>(ob);
    dcn_main_kernel<<<Bc * Hc, 256, SM_MAIN_FLOATS * 4>>>(bias, out);
}

// round 5
// speedup vs baseline: 3.2439x; 1.6925x over previous
#include <cuda_runtime.h>
#include <cuda_fp16.h>
#include <cstdint>

#define Hc 128
#define Wc 128
#define Cc 64
#define COUTc 64
#define Bc 4
#define NPIX (Bc*Hc*Wc)

// ------------------------------ scratch ------------------------------------
__device__ uint4  g_xH4[NPIX*8];        // NHWC fp16 input (8 uint4 = 64c/px)
__device__ float2 g_offs2[9*NPIX];      // offsets [tap][pix] (dy,dx)
__device__ uint4  g_wH4[9*64*8];        // main weights fp16 [tap][co][c]
__device__ uint4  g_owH4[9*24*8];       // offset weights fp16 [tap][o24][c]

// ------------------------------ helpers ------------------------------------
__device__ __forceinline__ void mma16(float* d, const uint32_t* a,
                                      uint32_t b0, uint32_t b1) {
    asm volatile(
        "mma.sync.aligned.m16n8k16.row.col.f32.f16.f16.f32 "
        "{%0,%1,%2,%3}, {%4,%5,%6,%7}, {%8,%9}, {%0,%1,%2,%3};"
        : "+f"(d[0]), "+f"(d[1]), "+f"(d[2]), "+f"(d[3])
        : "r"(a[0]), "r"(a[1]), "r"(a[2]), "r"(a[3]), "r"(b0), "r"(b1));
}

// ---------------------------------------------------------------------------
// Kernel 1: prep. blocks 0..511: NCHW->NHWC fp16 transpose; 512+: weights.
// ---------------------------------------------------------------------------
__global__ void __launch_bounds__(256) prep_kernel(
    const float* __restrict__ x, const float* __restrict__ w,
    const float* __restrict__ ow)
{
    int bid = blockIdx.x, tid = threadIdx.x;
    if (bid < 512) {
        __shared__ float sm[64 * 129];
        int b = bid >> 7, y = bid & 127;
        #pragma unroll
        for (int i = 0; i < 32; ++i) {
            int idx = tid + 256 * i;
            int c = idx >> 7, xx = idx & 127;
            sm[c * 129 + xx] = x[((size_t)(b * Cc + c) * Hc + y) * Wc + xx];
        }
        __syncthreads();
        half* op = (half*)g_xH4 + (size_t)(b * Hc + y) * Wc * Cc;
        #pragma unroll
        for (int i = 0; i < 32; ++i) {
            int idx = tid + 256 * i;
            int c = idx & 63, xx = idx >> 6;
            op[idx] = __float2half(sm[c * 129 + xx]);
        }
    } else {
        int t = (bid - 512) * 256 + tid;
        half* wh = (half*)g_wH4;
        for (int idx = t; idx < 9 * 64 * 64; idx += 36 * 256) {
            int tap = idx >> 12, r = idx & 4095;
            int co = r >> 6, c = r & 63;
            wh[idx] = __float2half(w[(co * Cc + c) * 9 + tap]);
        }
        half* oh = (half*)g_owH4;
        for (int idx = t; idx < 9 * 24 * 64; idx += 36 * 256) {
            int tap = idx / 1536;
            int r = idx - tap * 1536;
            int o = r >> 6, c = r & 63;
            oh[idx] = (o < 18) ? __float2half(ow[(o * Cc + c) * 9 + tap])
                               : __float2half(0.f);
        }
    }
}

// ---------------------------------------------------------------------------
// Kernel 2: offset conv as implicit GEMM (fp16 mma, fp32 accum).
// Block = 1 image row (128 px), 256 threads, warp tile 16px x 24ch.
// smem words: xrow[130][36] @0 (4680) | owsm[3 tap][24][36] @4680 (2592)
// ---------------------------------------------------------------------------
__global__ void __launch_bounds__(256) offset_conv_kernel(
    const float* __restrict__ ob)
{
    extern __shared__ uint32_t smw[];
    uint32_t* xroww = smw;
    uint32_t* oww   = smw + 4680;

    int tid = threadIdx.x, warp = tid >> 5, lane = tid & 31;
    int g = lane >> 2, tg = lane & 3;
    int blk = blockIdx.x, b = blk >> 7, y = blk & 127;

    float acc[3][4];
    #pragma unroll
    for (int nt = 0; nt < 3; ++nt) {
        int col = 8 * nt + 2 * tg;
        float b0 = (col < 18) ? __ldg(&ob[col]) : 0.f;
        float b1 = (col + 1 < 18) ? __ldg(&ob[col + 1]) : 0.f;
        acc[nt][0] = b0; acc[nt][1] = b1; acc[nt][2] = b0; acc[nt][3] = b1;
    }

    for (int ky = 0; ky < 3; ++ky) {
        int yy = y + ky - 1;
        if (yy < 0 || yy >= Hc) continue;   // uniform per block
        __syncthreads();
        // stage padded fp16 input row (130 px x 8 uint4)
        uint4* xd = (uint4*)xroww;
        #pragma unroll
        for (int i = 0; i < 5; ++i) {
            int j4 = tid + 256 * i;
            if (j4 < 1040) {
                int xi = j4 >> 3, cg = j4 & 7, x = xi - 1;
                uint4 v = make_uint4(0u, 0u, 0u, 0u);
                if (x >= 0 && x < Wc)
                    v = g_xH4[((size_t)(b * Hc + yy) * Wc + x) * 8 + cg];
                xd[xi * 9 + cg] = v;
            }
        }
        // stage 3 taps of weights [o24][c64]
        uint4* od = (uint4*)oww;
        #pragma unroll
        for (int i = 0; i < 3; ++i) {
            int j4 = tid + 256 * i;
            if (j4 < 576) {
                int tap = j4 / 192, r = j4 - tap * 192;
                int o = r >> 3, seg = r & 7;
                od[tap * 216 + o * 9 + seg] = g_owH4[(ky * 3 + tap) * 192 + r];
            }
        }
        __syncthreads();
        #pragma unroll
        for (int kx = 0; kx < 3; ++kx) {
            const uint32_t* ww = oww + kx * 864;
            int xb = warp * 16 + g + kx;
            #pragma unroll
            for (int kk = 0; kk < 4; ++kk) {
                int kof = kk * 8 + tg;
                uint32_t a[4];
                a[0] = xroww[xb * 36 + kof];
                a[1] = xroww[(xb + 8) * 36 + kof];
                a[2] = xroww[xb * 36 + kof + 4];
                a[3] = xroww[(xb + 8) * 36 + kof + 4];
                #pragma unroll
                for (int nt = 0; nt < 3; ++nt) {
                    int co = 8 * nt + g;
                    uint32_t b0 = ww[co * 36 + kof];
                    uint32_t b1 = ww[co * 36 + kof + 4];
                    mma16(acc[nt], a, b0, b1);
                }
            }
        }
    }

    int pix0 = blk * 128;
    #pragma unroll
    for (int nt = 0; nt < 3; ++nt) {
        int col = 8 * nt + 2 * tg;
        if (col < 18) {
            int tap = col >> 1;
            int p = warp * 16 + g;
            g_offs2[(size_t)tap * NPIX + pix0 + p] =
                make_float2(acc[nt][0], acc[nt][1]);
            g_offs2[(size_t)tap * NPIX + pix0 + p + 8] =
                make_float2(acc[nt][2], acc[nt][3]);
        }
    }
}

// ---------------------------------------------------------------------------
// Kernel 3: fused deformable sampling + fp16 mma GEMM, double-buffered.
// Block = 1 image row (128 px) x 64 co, 256 threads (8 warps).
// Warp tile: 32px (2 m16) x 32co (4 n8). ONE barrier per tap.
// smem words: patch[2][128][36] @0 (9216) | wsm[2][64][36] @9216 (4608)
// total 13824 words = 55296 B
// ---------------------------------------------------------------------------
__global__ void __launch_bounds__(256, 3) dcn_main_kernel(
    const float* __restrict__ bias, float* __restrict__ out)
{
    extern __shared__ uint32_t smw[];
    uint32_t* patchw = smw;            // [2][4608]
    uint32_t* wsmw   = smw + 9216;     // [2][2304]

    int tid = threadIdx.x, warp = tid >> 5, lane = tid & 31;
    int g = lane >> 2, tg = lane & 3;
    int mgrp = warp >> 1, ngrp = warp & 1;
    int blk = blockIdx.x, b = blk >> 7, y = blk & 127;
    int s_cg = tid & 7, s_p0 = tid >> 3;

    float acc[2][4][4];
    #pragma unroll
    for (int mt = 0; mt < 2; ++mt)
        #pragma unroll
        for (int nt = 0; nt < 4; ++nt)
            #pragma unroll
            for (int j = 0; j < 4; ++j) acc[mt][nt][j] = 0.f;

    for (int k = 0; k < 9; ++k) {
        int buf = k & 1;
        // stage weight tile [co][c] fp16 into wsm[buf]
        {
            uint4* dst = (uint4*)(wsmw + buf * 2304);
            const uint4* src = g_wH4 + k * 512;
            #pragma unroll
            for (int i = 0; i < 2; ++i) {
                int j4 = tid + 256 * i;
                int co = j4 >> 3, seg = j4 & 7;
                dst[co * 9 + seg] = src[j4];
            }
        }
        // sample into patch[buf] (coords computed inline)
        {
            uint4* pdst = (uint4*)(patchw + buf * 4608);
            int ky = k / 3, kx = k - ky * 3;
            #pragma unroll
            for (int i = 0; i < 4; ++i) {
                int p = s_p0 + 32 * i;
                float2 d2 = __ldg(&g_offs2[(size_t)k * NPIX + blk * 128 + p]);
                float py  = (float)(y - 1 + ky) + d2.x;
                float pxx = (float)(p - 1 + kx) + d2.y;
                float fy = floorf(py), fx = floorf(pxx);
                float ly = py - fy, lx = pxx - fx;
                int y0 = (int)fy, xq = (int)fx;
                bool vy0 = (y0 >= 0) & (y0 < Hc);
                bool vy1 = (y0 + 1 >= 0) & (y0 + 1 < Hc);
                bool vx0 = (xq >= 0) & (xq < Wc);
                bool vx1 = (xq + 1 >= 0) & (xq + 1 < Wc);
                float w00 = (1.f - ly) * (1.f - lx) * (float)(vy0 && vx0);
                float w01 = (1.f - ly) * lx         * (float)(vy0 && vx1);
                float w10 = ly * (1.f - lx)         * (float)(vy1 && vx0);
                float w11 = ly * lx                 * (float)(vy1 && vx1);
                int yc0 = min(max(y0, 0), Hc - 1);
                int yc1 = min(max(y0 + 1, 0), Hc - 1);
                int xc0 = min(max(xq, 0), Wc - 1);
                int xc1 = min(max(xq + 1, 0), Wc - 1);
                int r0 = (b * Hc + yc0) * Wc, r1 = (b * Hc + yc1) * Wc;
                uint4 q00 = g_xH4[(size_t)(r0 + xc0) * 8 + s_cg];
                uint4 q01 = g_xH4[(size_t)(r0 + xc1) * 8 + s_cg];
                uint4 q10 = g_xH4[(size_t)(r1 + xc0) * 8 + s_cg];
                uint4 q11 = g_xH4[(size_t)(r1 + xc1) * 8 + s_cg];
                const half2* h00 = (const half2*)&q00;
                const half2* h01 = (const half2*)&q01;
                const half2* h10 = (const half2*)&q10;
                const half2* h11 = (const half2*)&q11;
                uint4 r;
                half2* hr = (half2*)&r;
                #pragma unroll
                for (int j = 0; j < 4; ++j) {
                    float2 f00 = __half22float2(h00[j]);
                    float2 f01 = __half22float2(h01[j]);
                    float2 f10 = __half22float2(h10[j]);
                    float2 f11 = __half22float2(h11[j]);
                    float rx = w00*f00.x + w01*f01.x + w10*f10.x + w11*f11.x;
                    float ry = w00*f00.y + w01*f01.y + w10*f10.y + w11*f11.y;
                    hr[j] = __floats2half2_rn(rx, ry);
                }
                pdst[p * 9 + s_cg] = r;
            }
        }
        __syncthreads();
        // GEMM from patch[buf], wsm[buf]
        {
            const uint32_t* pw = patchw + buf * 4608;
            const uint32_t* ww = wsmw + buf * 2304;
            #pragma unroll
            for (int kk = 0; kk < 4; ++kk) {
                int kof = kk * 8 + tg;
                uint32_t a[2][4];
                #pragma unroll
                for (int mt = 0; mt < 2; ++mt) {
                    int r0 = mgrp * 32 + 16 * mt + g;
                    a[mt][0] = pw[r0 * 36 + kof];
                    a[mt][1] = pw[(r0 + 8) * 36 + kof];
                    a[mt][2] = pw[r0 * 36 + kof + 4];
                    a[mt][3] = pw[(r0 + 8) * 36 + kof + 4];
                }
                #pragma unroll
                for (int nt = 0; nt < 4; ++nt) {
                    int co = ngrp * 32 + 8 * nt + g;
                    uint32_t b0 = ww[co * 36 + kof];
                    uint32_t b1 = ww[co * 36 + kof + 4];
                    mma16(acc[0][nt], a[0], b0, b1);
                    mma16(acc[1][nt], a[1], b0, b1);
                }
            }
        }
    }

    // epilogue: transpose through smem (stride 132 floats), add bias, store
    __syncthreads();
    float* O = (float*)smw;   // 64*132 = 8448 floats = 33792B < 55296B
    #pragma unroll
    for (int mt = 0; mt < 2; ++mt)
        #pragma unroll
        for (int nt = 0; nt < 4; ++nt) {
            int row = mgrp * 32 + 16 * mt + g;
            int col = ngrp * 32 + 8 * nt + 2 * tg;
            float b0 = __ldg(&bias[col]), b1 = __ldg(&bias[col + 1]);
            O[col * 132 + row]           = acc[mt][nt][0] + b0;
            O[(col + 1) * 132 + row]     = acc[mt][nt][1] + b1;
            O[col * 132 + row + 8]       = acc[mt][nt][2] + b0;
            O[(col + 1) * 132 + row + 8] = acc[mt][nt][3] + b1;
        }
    __syncthreads();
    #pragma unroll
    for (int i = 0; i < 8; ++i) {
        int j4 = tid + 256 * i;
        int co = j4 >> 5, xq = j4 & 31;
        float4 v = *(float4*)&O[co * 132 + xq * 4];
        *(float4*)&out[(((size_t)b * COUTc + co) * Hc + y) * Wc + xq * 4] = v;
    }
}

// ---------------------------------------------------------------------------
extern "C" void kernel_launch(void* const* d_in, const int* in_sizes, int n_in,
                              void* d_out, int out_size)
{
    const float* x      = (const float*)d_in[0];
    const float* weight = (const float*)d_in[1];
    const float* bias   = (const float*)d_in[2];
    const float* ow     = (const float*)d_in[3];
    const float* ob     = (const float*)d_in[4];
    float* out = (float*)d_out;

    static int configured = 0;
    if (!configured) {
        cudaFuncSetAttribute(offset_conv_kernel,
            cudaFuncAttributeMaxDynamicSharedMemorySize, 7272 * 4);
        cudaFuncSetAttribute(dcn_main_kernel,
            cudaFuncAttributeMaxDynamicSharedMemorySize, 13824 * 4);
        configured = 1;
    }

    prep_kernel<<<512 + 36, 256>>>(x, weight, ow);
    offset_conv_kernel<<<Bc * Hc, 256, 7272 * 4>>>(ob);
    dcn_main_kernel<<<Bc * Hc, 256, 13824 * 4>>>(bias, out);
}